// round 4
// baseline (speedup 1.0000x reference)
#include <cuda_runtime.h>
#include <cuda_bf16.h>
#include <math.h>

// Problem constants
#define BATCH 32768
#define SNODES 16
#define DIN 128
#define HDIM 64
#define ODIM 32
#define MNODES 16

// Shared memory layout (floats) for main kernel
#define OFF_WT 0          // 64 x 128 transposed W (swizzled)
#define OFF_SF 8192       // 16 batches x 16 rows x 128 (swizzled)
#define OFF_ZS 40960      // 3 x 64 x 32
#define OFF_Y  47104      // 16 groups x 3 x 64
#define OFF_B  50176      // 64 bias
#define SMEM_FLOATS 50240
#define SMEM_BYTES (SMEM_FLOATS * 4)

typedef unsigned long long u64;

// packed f32x2 FMA: d.lo = a.lo*b.lo + c.lo ; d.hi = a.hi*b.hi + c.hi
#define FMA_F32X2(d, a, b) \
    asm("fma.rn.f32x2 %0, %1, %2, %0;" : "+l"(d) : "l"(a), "l"(b))

// Scratch (device globals; no allocation allowed)
__device__ float g_zs[3 * HDIM * ODIM];          // zs per step
__device__ float g_acc[(size_t)BATCH * ODIM];    // pre-BN accumulator (x3)
__device__ float g_p1[256 * ODIM];
__device__ float g_p2[256 * ODIM];
__device__ float g_mean[ODIM];
__device__ float g_scale[ODIM];
__device__ float g_shift[ODIM];

// ---------------------------------------------------------------------------
// Prep: build hidden-graph step matrices zs0/zs1/zs2 (64x32 each).
// ---------------------------------------------------------------------------
__global__ void prep_kernel(const float* __restrict__ adj_hidden,
                            const float* __restrict__ fh) {
    __shared__ float A[MNODES][MNODES][ODIM];   // 32 KB
    __shared__ float dA[MNODES][ODIM];
    __shared__ float d2[MNODES][ODIM];
    int t = threadIdx.x;  // 128 threads

    for (int idx = t; idx < MNODES * MNODES * ODIM; idx += 128)
        ((float*)A)[idx] = 0.f;
    __syncthreads();

    for (int idx = t; idx < 120 * ODIM; idx += 128) {
        int p = idx >> 5, o = idx & 31;
        int i = 0, rem = p;
        while (rem >= (MNODES - 1 - i)) { rem -= (MNODES - 1 - i); i++; }
        int j = i + 1 + rem;
        float v = fmaxf(adj_hidden[idx], 0.f);
        A[i][j][o] = v;
        A[j][i][o] = v;
    }
    __syncthreads();

    for (int idx = t; idx < MNODES * ODIM; idx += 128) {
        int q = idx >> 5, o = idx & 31;
        float s = 0.f;
        #pragma unroll
        for (int m = 0; m < MNODES; m++) s += A[m][q][o];
        dA[q][o] = s;
    }
    __syncthreads();

    for (int idx = t; idx < MNODES * ODIM; idx += 128) {
        int q = idx >> 5, o = idx & 31;
        float s = 0.f;
        #pragma unroll
        for (int p = 0; p < MNODES; p++) s += A[p][q][o] * dA[p][o];
        d2[q][o] = s;
    }
    __syncthreads();

    for (int idx = t; idx < HDIM * ODIM; idx += 128) {
        int h = idx >> 5, o = idx & 31;
        float s0 = 0.f, s1 = 0.f, s2 = 0.f;
        #pragma unroll
        for (int m = 0; m < MNODES; m++) {
            float z = fh[m * (HDIM * ODIM) + h * ODIM + o];
            s0 += z;
            s1 += dA[m][o] * z;
            s2 += d2[m][o] * z;
        }
        g_zs[idx] = s0;
        g_zs[2048 + idx] = s1;
        g_zs[4096 + idx] = s2;
    }
}

// ---------------------------------------------------------------------------
// Main kernel: 16 batches/block, 16 threads/batch, 8x8 register tiles.
// GEMM inner loop uses packed fma.rn.f32x2 with k-pair packing: a float4
// (k0..k3) is two f32x2 pairs; acc.lo accumulates even-k, acc.hi odd-k.
// ---------------------------------------------------------------------------
__global__ void __launch_bounds__(256, 1)
main_kernel(const float* __restrict__ adj, const float* __restrict__ feat,
            const float* __restrict__ W, const float* __restrict__ b_in) {
    extern __shared__ float sm[];
    int tid = threadIdx.x;
    int blk = blockIdx.x;

    // Stage W transposed [h][128], XOR-swizzled on 16B granularity by (h>>3)&7
    #pragma unroll 4
    for (int it = 0; it < 32; it++) {
        int idx = it * 256 + tid;
        int h = idx & 63, k = idx >> 6;
        float w = W[k * 64 + h];
        sm[OFF_WT + h * 128 + ((((k >> 2) ^ ((h >> 3) & 7)) << 2) | (k & 3))] = w;
    }
    // Stage features: 16 batches x 16 rows x 128, swizzled by (row>>3)&7
    {
        const float4* src = (const float4*)(feat + (size_t)blk * 16 * SNODES * DIN);
        #pragma unroll 4
        for (int it = 0; it < 32; it++) {
            int idx = it * 256 + tid;          // = r*32 + kq
            int kq = idx & 31, r = idx >> 5;
            float4 v = src[idx];
            *(float4*)&sm[OFF_SF + r * 128 + ((kq ^ ((r >> 3) & 7)) << 2)] = v;
        }
    }
    for (int idx = tid; idx < 6144; idx += 256) sm[OFF_ZS + idx] = g_zs[idx];
    if (tid < 64) sm[OFF_B + tid] = b_in[tid];
    __syncthreads();

    int g = tid >> 4, tg = tid & 15;
    int b = blk * 16 + g;
    int lane = tid & 31;
    int s_base = (tg >> 3) << 3;   // 0 or 8
    int h_base = (tg & 7) << 3;    // 0..56

    // Degree weights from adj (column sums; adj symmetric so == row sums)
    const float* adjb = adj + (size_t)b * (SNODES * SNODES);
    float dsum = 0.f;
    #pragma unroll
    for (int s = 0; s < 16; s++) dsum += adjb[s * 16 + tg];
    float esum = 0.f;
    #pragma unroll
    for (int u = 0; u < 16; u++) {
        float du = __shfl_sync(0xffffffffu, dsum, (lane & 16) | u);
        esum += adjb[u * 16 + tg] * du;
    }
    float w1v[8], w2v[8];
    #pragma unroll
    for (int i = 0; i < 8; i++) {
        w1v[i] = __shfl_sync(0xffffffffu, dsum, (lane & 16) | (s_base + i));
        w2v[i] = __shfl_sync(0xffffffffu, esum, (lane & 16) | (s_base + i));
    }

    // GEMM: 8 s-rows x 8 h-cols per thread over k=128, packed f32x2 pairs.
    u64 acc[8][8];
    #pragma unroll
    for (int i = 0; i < 8; i++)
        #pragma unroll
        for (int j = 0; j < 8; j++) acc[i][j] = 0ull;

    const float* fbase = sm + OFF_SF + (g * 16 + s_base) * 128;
    const float* wbase = sm + OFF_WT + h_base * 128;
    int fsw = ((g * 16 + s_base) >> 3) & 7;
    int wsw = tg & 7;

    #pragma unroll 1
    for (int kq = 0; kq < 32; kq++) {
        int kf = (kq ^ fsw) << 2;
        int kw = (kq ^ wsw) << 2;
        ulonglong2 fv[8];
        #pragma unroll
        for (int i = 0; i < 8; i++)
            fv[i] = *(const ulonglong2*)(fbase + i * 128 + kf);
        #pragma unroll
        for (int j = 0; j < 8; j++) {
            ulonglong2 wv = *(const ulonglong2*)(wbase + j * 128 + kw);
            #pragma unroll
            for (int i = 0; i < 8; i++) {
                FMA_F32X2(acc[i][j], fv[i].x, wv.x);
                FMA_F32X2(acc[i][j], fv[i].y, wv.y);
            }
        }
    }

    // Epilogue: unpack (even-k, odd-k) halves, bias + sigmoid + node sums
    float y0[8], y1[8], y2[8];
    #pragma unroll
    for (int j = 0; j < 8; j++) { y0[j] = 0.f; y1[j] = 0.f; y2[j] = 0.f; }
    #pragma unroll
    for (int i = 0; i < 8; i++)
        #pragma unroll
        for (int j = 0; j < 8; j++) {
            float lo = __uint_as_float((unsigned)(acc[i][j] & 0xffffffffull));
            float hi = __uint_as_float((unsigned)(acc[i][j] >> 32));
            float v = lo + hi + sm[OFF_B + h_base + j];
            v = 1.f / (1.f + __expf(-v));
            y0[j] += v;
            y1[j] += w1v[i] * v;
            y2[j] += w2v[i] * v;
        }
    // reduce over the two s-halves (partner lane = lane ^ 8, same group)
    #pragma unroll
    for (int j = 0; j < 8; j++) {
        y0[j] += __shfl_xor_sync(0xffffffffu, y0[j], 8);
        y1[j] += __shfl_xor_sync(0xffffffffu, y1[j], 8);
        y2[j] += __shfl_xor_sync(0xffffffffu, y2[j], 8);
    }
    if (tg < 8) {
        float* yp = sm + OFF_Y + g * 192;
        #pragma unroll
        for (int j = 0; j < 8; j++) {
            yp[h_base + j] = y0[j];
            yp[64 + h_base + j] = y1[j];
            yp[128 + h_base + j] = y2[j];
        }
    }
    __syncwarp();

    // Contraction with zs: 2 outputs per thread
    float a1 = 0.f, a2 = 0.f;
    const float* yp = sm + OFF_Y + g * 192;
    #pragma unroll 1
    for (int st = 0; st < 3; st++) {
        #pragma unroll 8
        for (int h = 0; h < 64; h++) {
            float yv = yp[st * 64 + h];
            a1 += yv * sm[OFF_ZS + st * 2048 + h * 32 + tg];
            a2 += yv * sm[OFF_ZS + st * 2048 + h * 32 + tg + 16];
        }
    }
    g_acc[(size_t)b * 32 + tg] = a1;
    g_acc[(size_t)b * 32 + tg + 16] = a2;
}

// ---------------------------------------------------------------------------
// Deterministic two-stage reductions for BatchNorm stats (two-pass variance)
// ---------------------------------------------------------------------------
__global__ void red1_kernel() {
    __shared__ float s[256];
    int t = threadIdx.x, blk = blockIdx.x;
    int o = t & 31, rg = t >> 5;
    float local = 0.f;
    int base = blk * 128;
    #pragma unroll
    for (int j = 0; j < 16; j++)
        local += g_acc[(size_t)(base + rg + j * 8) * 32 + o];
    s[t] = local;
    __syncthreads();
    if (t < 32) {
        float tot = 0.f;
        #pragma unroll
        for (int j = 0; j < 8; j++) tot += s[j * 32 + t];
        g_p1[blk * 32 + t] = tot;
    }
}

__global__ void red1b_kernel() {
    __shared__ float s[256];
    int t = threadIdx.x;
    int o = t & 31, rg = t >> 5;
    float local = 0.f;
    #pragma unroll
    for (int j = 0; j < 32; j++) local += g_p1[(rg + j * 8) * 32 + o];
    s[t] = local;
    __syncthreads();
    if (t < 32) {
        float tot = 0.f;
        #pragma unroll
        for (int j = 0; j < 8; j++) tot += s[j * 32 + t];
        g_mean[t] = tot * (1.f / (3.f * (float)BATCH));
    }
}

__global__ void red2_kernel() {
    __shared__ float s[256];
    int t = threadIdx.x, blk = blockIdx.x;
    int o = t & 31, rg = t >> 5;
    float mu = g_mean[o];
    float local = 0.f;
    int base = blk * 128;
    #pragma unroll
    for (int j = 0; j < 16; j++) {
        float v = g_acc[(size_t)(base + rg + j * 8) * 32 + o] * (1.f / 3.f) - mu;
        local += v * v;
    }
    s[t] = local;
    __syncthreads();
    if (t < 32) {
        float tot = 0.f;
        #pragma unroll
        for (int j = 0; j < 8; j++) tot += s[j * 32 + t];
        g_p2[blk * 32 + t] = tot;
    }
}

__global__ void red2b_kernel(const float* __restrict__ gamma,
                             const float* __restrict__ beta) {
    __shared__ float s[256];
    int t = threadIdx.x;
    int o = t & 31, rg = t >> 5;
    float local = 0.f;
    #pragma unroll
    for (int j = 0; j < 32; j++) local += g_p2[(rg + j * 8) * 32 + o];
    s[t] = local;
    __syncthreads();
    if (t < 32) {
        float tot = 0.f;
        #pragma unroll
        for (int j = 0; j < 8; j++) tot += s[j * 32 + t];
        float var = tot * (1.f / (float)BATCH);
        float istd = rsqrtf(var + 1e-5f);
        float sc = gamma[t] * istd;
        g_scale[t] = sc;
        g_shift[t] = beta[t] - g_mean[t] * sc;
    }
}

__global__ void fin_kernel(float* __restrict__ out) {
    int idx = blockIdx.x * 256 + threadIdx.x;   // float4 index, 262144 total
    float4 a = ((const float4*)g_acc)[idx];
    int o0 = (idx & 7) << 2;
    float4 r;
    {
        float v = a.x * (1.f / 3.f) * g_scale[o0 + 0] + g_shift[o0 + 0];
        r.x = 1.f / (1.f + __expf(-v));
    }
    {
        float v = a.y * (1.f / 3.f) * g_scale[o0 + 1] + g_shift[o0 + 1];
        r.y = 1.f / (1.f + __expf(-v));
    }
    {
        float v = a.z * (1.f / 3.f) * g_scale[o0 + 2] + g_shift[o0 + 2];
        r.z = 1.f / (1.f + __expf(-v));
    }
    {
        float v = a.w * (1.f / 3.f) * g_scale[o0 + 3] + g_shift[o0 + 3];
        r.w = 1.f / (1.f + __expf(-v));
    }
    ((float4*)out)[idx] = r;
}

// ---------------------------------------------------------------------------
extern "C" void kernel_launch(void* const* d_in, const int* in_sizes, int n_in,
                              void* d_out, int out_size) {
    const float* adj   = (const float*)d_in[0];
    const float* feat  = (const float*)d_in[1];
    const float* W     = (const float*)d_in[2];
    const float* b_in  = (const float*)d_in[3];
    const float* fh    = (const float*)d_in[4];
    const float* ah    = (const float*)d_in[5];
    const float* gamma = (const float*)d_in[6];
    const float* beta  = (const float*)d_in[7];
    float* out = (float*)d_out;

    cudaFuncSetAttribute(main_kernel,
                         cudaFuncAttributeMaxDynamicSharedMemorySize, SMEM_BYTES);

    prep_kernel<<<1, 128>>>(ah, fh);
    main_kernel<<<BATCH / 16, 256, SMEM_BYTES>>>(adj, feat, W, b_in);
    red1_kernel<<<256, 256>>>();
    red1b_kernel<<<1, 256>>>();
    red2_kernel<<<256, 256>>>();
    red2b_kernel<<<1, 256>>>(gamma, beta);
    fin_kernel<<<1024, 256>>>(out);
}

// round 6
// speedup vs baseline: 1.4861x; 1.4861x over previous
#include <cuda_runtime.h>
#include <cuda_bf16.h>
#include <math.h>
#include <stdint.h>

// Problem constants
#define BATCH 32768
#define SNODES 16
#define DIN 128
#define HDIM 64
#define ODIM 32
#define MNODES 16
#define NBATCH_TILE 8           // batches per CTA (128 rows = 8 x 16 nodes)

// smem word-offsets (u32 units)
#define A_STRIDE 68             // words per A row  (conflict-free frag loads)
#define B_STRIDE 72             // words per B kpair-row
#define AHI_W 0                 // 128 x 68
#define ALO_W 8704
#define BHI_W 17408             // 64 x 72
#define BLO_W 22016
#define Y_W   26624             // 8 batches x 3 terms x 64 h
#define W_W   28160             // 8 x (16 w1 | 16 w2)
#define BIAS_W 28416            // 64
#define SMEM_WORDS 28480
#define SMEM_BYTES (SMEM_WORDS * 4)

// bf16 mma: D(16x8,f32) += A(16x16,row) * B(16x8,col)
#define MMA_BF16(d, a, b)                                                     \
    asm volatile("mma.sync.aligned.m16n8k16.row.col.f32.bf16.bf16.f32 "       \
        "{%0,%1,%2,%3}, {%4,%5,%6,%7}, {%8,%9}, {%0,%1,%2,%3};"               \
        : "+f"((d)[0]), "+f"((d)[1]), "+f"((d)[2]), "+f"((d)[3])              \
        : "r"((a)[0]), "r"((a)[1]), "r"((a)[2]), "r"((a)[3]),                 \
          "r"((b)[0]), "r"((b)[1]))

// Scratch (device globals; no allocation allowed)
__device__ float g_zs[3 * HDIM * ODIM];
__device__ float g_acc[(size_t)BATCH * ODIM];
__device__ float g_p1[256 * ODIM];
__device__ float g_p2[256 * ODIM];
__device__ float g_mean[ODIM];
__device__ float g_scale[ODIM];
__device__ float g_shift[ODIM];

// split fp32 pair -> packed bf16x2 (hi, lo); .x (low 16 bits) = first elem
static __device__ __forceinline__ void cvt_hilo2(float a, float b,
                                                 uint32_t& hi, uint32_t& lo) {
    __nv_bfloat16 ha = __float2bfloat16(a);
    __nv_bfloat16 hb = __float2bfloat16(b);
    float ra = a - __bfloat162float(ha);
    float rb = b - __bfloat162float(hb);
    __nv_bfloat16 la = __float2bfloat16(ra);
    __nv_bfloat16 lb = __float2bfloat16(rb);
    __nv_bfloat162 ph; ph.x = ha; ph.y = hb;
    __nv_bfloat162 pl; pl.x = la; pl.y = lb;
    hi = *(uint32_t*)&ph;
    lo = *(uint32_t*)&pl;
}

static __device__ __forceinline__ float sigmoidf_fast(float v) {
    return 1.f / (1.f + __expf(-v));
}

// ---------------------------------------------------------------------------
// Prep: build hidden-graph step matrices zs0/zs1/zs2 (64x32 each).
// ---------------------------------------------------------------------------
__global__ void prep_kernel(const float* __restrict__ adj_hidden,
                            const float* __restrict__ fh) {
    __shared__ float A[MNODES][MNODES][ODIM];
    __shared__ float dA[MNODES][ODIM];
    __shared__ float d2[MNODES][ODIM];
    int t = threadIdx.x;

    for (int idx = t; idx < MNODES * MNODES * ODIM; idx += 128)
        ((float*)A)[idx] = 0.f;
    __syncthreads();

    for (int idx = t; idx < 120 * ODIM; idx += 128) {
        int p = idx >> 5, o = idx & 31;
        int i = 0, rem = p;
        while (rem >= (MNODES - 1 - i)) { rem -= (MNODES - 1 - i); i++; }
        int j = i + 1 + rem;
        float v = fmaxf(adj_hidden[idx], 0.f);
        A[i][j][o] = v;
        A[j][i][o] = v;
    }
    __syncthreads();

    for (int idx = t; idx < MNODES * ODIM; idx += 128) {
        int q = idx >> 5, o = idx & 31;
        float s = 0.f;
        #pragma unroll
        for (int m = 0; m < MNODES; m++) s += A[m][q][o];
        dA[q][o] = s;
    }
    __syncthreads();

    for (int idx = t; idx < MNODES * ODIM; idx += 128) {
        int q = idx >> 5, o = idx & 31;
        float s = 0.f;
        #pragma unroll
        for (int p = 0; p < MNODES; p++) s += A[p][q][o] * dA[p][o];
        d2[q][o] = s;
    }
    __syncthreads();

    for (int idx = t; idx < HDIM * ODIM; idx += 128) {
        int h = idx >> 5, o = idx & 31;
        float s0 = 0.f, s1 = 0.f, s2 = 0.f;
        #pragma unroll
        for (int m = 0; m < MNODES; m++) {
            float z = fh[m * (HDIM * ODIM) + h * ODIM + o];
            s0 += z;
            s1 += dA[m][o] * z;
            s2 += d2[m][o] * z;
        }
        g_zs[idx] = s0;
        g_zs[2048 + idx] = s1;
        g_zs[4096 + idx] = s2;
    }
}

// ---------------------------------------------------------------------------
// Main kernel: 128x64x128 GEMM tile per CTA via mma.sync bf16 split-precision
// (D = Ahi*Bhi + Ahi*Blo + Alo*Bhi, fp32 accumulate, register-resident).
// ---------------------------------------------------------------------------
__global__ void __launch_bounds__(256, 2)
main_kernel(const float* __restrict__ adj, const float* __restrict__ feat,
            const float* __restrict__ W, const float* __restrict__ b_in) {
    extern __shared__ __align__(16) uint32_t sw[];
    float* smf = (float*)sw;
    int tid = threadIdx.x, wid = tid >> 5, lane = tid & 31;
    int blk = blockIdx.x;

    // ---- stage A = features tile (128 rows x 128 k) as bf16 hi/lo k-pairs
    {
        const float4* src = (const float4*)(feat + (size_t)blk * 128 * DIN);
        #pragma unroll
        for (int i = 0; i < 16; i++) {
            int idx = tid + i * 256;           // float4 index within tile
            int row = idx >> 5, c = idx & 31;
            float4 v = src[idx];
            uint32_t h0, l0, h1, l1;
            cvt_hilo2(v.x, v.y, h0, l0);
            cvt_hilo2(v.z, v.w, h1, l1);
            int wbase = row * A_STRIDE + 2 * c;
            *(uint2*)&sw[AHI_W + wbase] = make_uint2(h0, h1);
            *(uint2*)&sw[ALO_W + wbase] = make_uint2(l0, l1);
        }
    }
    // ---- stage B: Bpack[kp][h] = (W[2kp][h], W[2kp+1][h]) bf16 hi/lo
    #pragma unroll
    for (int i = 0; i < 16; i++) {
        int idx = tid + i * 256;               // 64 kp x 64 h
        int kp = idx >> 6, h = idx & 63;
        float w0 = W[(2 * kp) * HDIM + h];
        float w1f = W[(2 * kp + 1) * HDIM + h];
        uint32_t hi, lo;
        cvt_hilo2(w0, w1f, hi, lo);
        sw[BHI_W + kp * B_STRIDE + h] = hi;
        sw[BLO_W + kp * B_STRIDE + h] = lo;
    }
    if (tid < 64) smf[BIAS_W + tid] = b_in[tid];
    // ---- node weights: w1 = colsum(adj), w2 = adj^T w1   (per batch)
    if (tid < 128) {
        int bg = tid >> 4, q = tid & 15;
        const float* adjb = adj + (size_t)(blk * NBATCH_TILE + bg) * 256;
        float dsum = 0.f;
        #pragma unroll
        for (int s = 0; s < 16; s++) dsum += adjb[s * 16 + q];
        smf[W_W + bg * 32 + q] = dsum;
        __syncwarp();
        float e = 0.f;
        #pragma unroll
        for (int u = 0; u < 16; u++) e += adjb[u * 16 + q] * smf[W_W + bg * 32 + u];
        smf[W_W + bg * 32 + 16 + q] = e;
    }
    __syncthreads();

    // ---- warp-tile MMA: warp covers rows [warp_m*32, +32), cols [warp_n*32, +32)
    int warp_m = wid & 3, warp_n = wid >> 2;
    int g = lane >> 2, tig = lane & 3;

    float d[2][4][4];
    #pragma unroll
    for (int mt = 0; mt < 2; mt++)
        #pragma unroll
        for (int nt = 0; nt < 4; nt++)
            #pragma unroll
            for (int r = 0; r < 4; r++) d[mt][nt][r] = 0.f;

    int a0base = (warp_m * 32 + g) * A_STRIDE + tig;
    int b0base = tig * B_STRIDE + warp_n * 32 + g;

    #pragma unroll 1
    for (int ks = 0; ks < 8; ks++) {
        uint32_t ah[2][4], al[2][4], bh[4][2], bl[4][2];
        #pragma unroll
        for (int mt = 0; mt < 2; mt++) {
            int base = a0base + mt * (16 * A_STRIDE) + ks * 8;
            ah[mt][0] = sw[AHI_W + base];
            ah[mt][1] = sw[AHI_W + base + 8 * A_STRIDE];
            ah[mt][2] = sw[AHI_W + base + 4];
            ah[mt][3] = sw[AHI_W + base + 8 * A_STRIDE + 4];
            al[mt][0] = sw[ALO_W + base];
            al[mt][1] = sw[ALO_W + base + 8 * A_STRIDE];
            al[mt][2] = sw[ALO_W + base + 4];
            al[mt][3] = sw[ALO_W + base + 8 * A_STRIDE + 4];
        }
        #pragma unroll
        for (int nt = 0; nt < 4; nt++) {
            int base = b0base + ks * (8 * B_STRIDE) + nt * 8;
            bh[nt][0] = sw[BHI_W + base];
            bh[nt][1] = sw[BHI_W + base + 4 * B_STRIDE];
            bl[nt][0] = sw[BLO_W + base];
            bl[nt][1] = sw[BLO_W + base + 4 * B_STRIDE];
        }
        #pragma unroll
        for (int mt = 0; mt < 2; mt++)
            #pragma unroll
            for (int nt = 0; nt < 4; nt++) {
                MMA_BF16(d[mt][nt], ah[mt], bh[nt]);
                MMA_BF16(d[mt][nt], ah[mt], bl[nt]);
                MMA_BF16(d[mt][nt], al[mt], bh[nt]);
            }
    }

    // ---- epilogue: bias + sigmoid + weighted node sums, all in-register.
    // D layout: d[mt][nt][0,1] rows g    cols 2tig,2tig+1
    //           d[mt][nt][2,3] rows g+8  (same cols), col base nbase+8nt
    #pragma unroll
    for (int mt = 0; mt < 2; mt++) {
        int batch = warp_m * 2 + mt;
        float w1g  = smf[W_W + batch * 32 + g];
        float w1g8 = smf[W_W + batch * 32 + g + 8];
        float w2g  = smf[W_W + batch * 32 + 16 + g];
        float w2g8 = smf[W_W + batch * 32 + 24 + g];
        float y0[8], y1[8], y2[8];
        #pragma unroll
        for (int nt = 0; nt < 4; nt++)
            #pragma unroll
            for (int c = 0; c < 2; c++) {
                int col = warp_n * 32 + nt * 8 + tig * 2 + c;
                float bias = smf[BIAS_W + col];
                float vg  = sigmoidf_fast(d[mt][nt][c] + bias);
                float vg8 = sigmoidf_fast(d[mt][nt][c + 2] + bias);
                int j = nt * 2 + c;
                y0[j] = vg + vg8;
                y1[j] = w1g * vg + w1g8 * vg8;
                y2[j] = w2g * vg + w2g8 * vg8;
            }
        // reduce over g (lanes stride 4): butterfly masks 4, 8, 16
        #pragma unroll
        for (int j = 0; j < 8; j++) {
            #pragma unroll
            for (int msk = 4; msk <= 16; msk <<= 1) {
                y0[j] += __shfl_xor_sync(0xffffffffu, y0[j], msk);
                y1[j] += __shfl_xor_sync(0xffffffffu, y1[j], msk);
                y2[j] += __shfl_xor_sync(0xffffffffu, y2[j], msk);
            }
        }
        if (g == 0) {
            #pragma unroll
            for (int j = 0; j < 8; j++) {
                int col = warp_n * 32 + (j >> 1) * 8 + tig * 2 + (j & 1);
                smf[Y_W + batch * 192 + col] = y0[j];
                smf[Y_W + batch * 192 + 64 + col] = y1[j];
                smf[Y_W + batch * 192 + 128 + col] = y2[j];
            }
        }
    }
    __syncthreads();

    // ---- acc[b,o] = sum_{term,h} y[term,h] * zs[term,h,o]
    {
        int bb = tid >> 5, o = tid & 31;
        const float* yp = smf + Y_W + bb * 192;
        float a = 0.f;
        #pragma unroll 8
        for (int th = 0; th < 192; th++)
            a += yp[th] * __ldg(&g_zs[th * 32 + o]);
        g_acc[(size_t)(blk * NBATCH_TILE + bb) * 32 + o] = a;
    }
}

// ---------------------------------------------------------------------------
// Deterministic two-stage reductions for BatchNorm stats (two-pass variance)
// ---------------------------------------------------------------------------
__global__ void red1_kernel() {
    __shared__ float s[256];
    int t = threadIdx.x, blk = blockIdx.x;
    int o = t & 31, rg = t >> 5;
    float local = 0.f;
    int base = blk * 128;
    #pragma unroll
    for (int j = 0; j < 16; j++)
        local += g_acc[(size_t)(base + rg + j * 8) * 32 + o];
    s[t] = local;
    __syncthreads();
    if (t < 32) {
        float tot = 0.f;
        #pragma unroll
        for (int j = 0; j < 8; j++) tot += s[j * 32 + t];
        g_p1[blk * 32 + t] = tot;
    }
}

__global__ void red1b_kernel() {
    __shared__ float s[256];
    int t = threadIdx.x;
    int o = t & 31, rg = t >> 5;
    float local = 0.f;
    #pragma unroll
    for (int j = 0; j < 32; j++) local += g_p1[(rg + j * 8) * 32 + o];
    s[t] = local;
    __syncthreads();
    if (t < 32) {
        float tot = 0.f;
        #pragma unroll
        for (int j = 0; j < 8; j++) tot += s[j * 32 + t];
        g_mean[t] = tot * (1.f / (3.f * (float)BATCH));
    }
}

__global__ void red2_kernel() {
    __shared__ float s[256];
    int t = threadIdx.x, blk = blockIdx.x;
    int o = t & 31, rg = t >> 5;
    float mu = g_mean[o];
    float local = 0.f;
    int base = blk * 128;
    #pragma unroll
    for (int j = 0; j < 16; j++) {
        float v = g_acc[(size_t)(base + rg + j * 8) * 32 + o] * (1.f / 3.f) - mu;
        local += v * v;
    }
    s[t] = local;
    __syncthreads();
    if (t < 32) {
        float tot = 0.f;
        #pragma unroll
        for (int j = 0; j < 8; j++) tot += s[j * 32 + t];
        g_p2[blk * 32 + t] = tot;
    }
}

__global__ void red2b_kernel(const float* __restrict__ gamma,
                             const float* __restrict__ beta) {
    __shared__ float s[256];
    int t = threadIdx.x;
    int o = t & 31, rg = t >> 5;
    float local = 0.f;
    #pragma unroll
    for (int j = 0; j < 32; j++) local += g_p2[(rg + j * 8) * 32 + o];
    s[t] = local;
    __syncthreads();
    if (t < 32) {
        float tot = 0.f;
        #pragma unroll
        for (int j = 0; j < 8; j++) tot += s[j * 32 + t];
        float var = tot * (1.f / (float)BATCH);
        float istd = rsqrtf(var + 1e-5f);
        float sc = gamma[t] * istd;
        g_scale[t] = sc;
        g_shift[t] = beta[t] - g_mean[t] * sc;
    }
}

__global__ void fin_kernel(float* __restrict__ out) {
    int idx = blockIdx.x * 256 + threadIdx.x;
    float4 a = ((const float4*)g_acc)[idx];
    int o0 = (idx & 7) << 2;
    float4 r;
    {
        float v = a.x * (1.f / 3.f) * g_scale[o0 + 0] + g_shift[o0 + 0];
        r.x = 1.f / (1.f + __expf(-v));
    }
    {
        float v = a.y * (1.f / 3.f) * g_scale[o0 + 1] + g_shift[o0 + 1];
        r.y = 1.f / (1.f + __expf(-v));
    }
    {
        float v = a.z * (1.f / 3.f) * g_scale[o0 + 2] + g_shift[o0 + 2];
        r.z = 1.f / (1.f + __expf(-v));
    }
    {
        float v = a.w * (1.f / 3.f) * g_scale[o0 + 3] + g_shift[o0 + 3];
        r.w = 1.f / (1.f + __expf(-v));
    }
    ((float4*)out)[idx] = r;
}

// ---------------------------------------------------------------------------
extern "C" void kernel_launch(void* const* d_in, const int* in_sizes, int n_in,
                              void* d_out, int out_size) {
    const float* adj   = (const float*)d_in[0];
    const float* feat  = (const float*)d_in[1];
    const float* W     = (const float*)d_in[2];
    const float* b_in  = (const float*)d_in[3];
    const float* fh    = (const float*)d_in[4];
    const float* ah    = (const float*)d_in[5];
    const float* gamma = (const float*)d_in[6];
    const float* beta  = (const float*)d_in[7];
    float* out = (float*)d_out;

    cudaFuncSetAttribute(main_kernel,
                         cudaFuncAttributeMaxDynamicSharedMemorySize, SMEM_BYTES);

    prep_kernel<<<1, 128>>>(ah, fh);
    main_kernel<<<BATCH / NBATCH_TILE, 256, SMEM_BYTES>>>(adj, feat, W, b_in);
    red1_kernel<<<256, 256>>>();
    red1b_kernel<<<1, 256>>>();
    red2_kernel<<<256, 256>>>();
    red2b_kernel<<<1, 256>>>(gamma, beta);
    fin_kernel<<<1024, 256>>>(out);
}